// round 1
// baseline (speedup 1.0000x reference)
#include <cuda_runtime.h>
#include <math.h>
#include <stdint.h>

#define T_STEPS 1024
#define BATCH   32
#define INP     512
#define HID     512
#define G4      2048   // 4*HID

// ---------------- scratch (static __device__ = allowed scratch) ----------------
__device__ float g_xw[(size_t)T_STEPS * G4 * BATCH]; // [t][col][b]   (256 MB)
__device__ float g_h[2][HID * BATCH];                // ping-pong h, layout [k][b]
__device__ unsigned int g_bar;                       // grid barrier counter

// ---------------- init: zero h0 and barrier (every launch -> graph-safe) -------
__global__ void lstm_init_kernel() {
    int idx = blockIdx.x * blockDim.x + threadIdx.x;
    int n = 2 * HID * BATCH;
    for (int i = idx; i < n; i += gridDim.x * blockDim.x)
        ((float*)g_h)[i] = 0.f;
    if (idx == 0) g_bar = 0u;
}

// ---------------- phase 1: xw[t][j][b] = sum_k x[t][b][k]*W[k][j] + bias[j] ----
__global__ __launch_bounds__(256) void xw_gemm_kernel(
    const float* __restrict__ x, const float* __restrict__ W,
    const float* __restrict__ bias)
{
    __shared__ float xs[32][36];   // [k][b], padded, 16B-aligned rows (36*4=144)
    __shared__ float ws[32][128];  // [k][j]

    const int t   = blockIdx.y;
    const int j0t = blockIdx.x * 128;
    const int tid = threadIdx.x;

    const int jg = tid & 31;       // 0..31 -> j group
    const int bg = tid >> 5;       // 0..7  -> b group
    const int jb = jg * 4;         // local j base
    const int bb = bg * 4;         // local b base

    float acc[4][4] = {};          // [b][j]

    const float* xt = x + (size_t)t * BATCH * INP;

    for (int k0 = 0; k0 < INP; k0 += 32) {
        // load x chunk (transpose into [k][b])
        {
            int b  = tid >> 3;
            int kk = (tid & 7) * 4;
            float4 v = *(const float4*)(xt + (size_t)b * INP + k0 + kk);
            xs[kk + 0][b] = v.x; xs[kk + 1][b] = v.y;
            xs[kk + 2][b] = v.z; xs[kk + 3][b] = v.w;
        }
        // load W chunk: 32 rows x 128 cols
        #pragma unroll
        for (int r = 0; r < 4; r++) {
            int kk = (tid >> 5) + 8 * r;
            int jj = (tid & 31) * 4;
            float4 v = *(const float4*)(W + (size_t)(k0 + kk) * G4 + j0t + jj);
            *(float4*)&ws[kk][jj] = v;
        }
        __syncthreads();

        #pragma unroll
        for (int kk = 0; kk < 32; kk++) {
            float4 xa = *(const float4*)&xs[kk][bb];   // broadcast within warp
            float4 wa = *(const float4*)&ws[kk][jb];   // conflict-free
            float xv[4] = {xa.x, xa.y, xa.z, xa.w};
            float wv[4] = {wa.x, wa.y, wa.z, wa.w};
            #pragma unroll
            for (int b = 0; b < 4; b++)
                #pragma unroll
                for (int j = 0; j < 4; j++)
                    acc[b][j] += xv[b] * wv[j];
        }
        __syncthreads();
    }

    float4 bv = *(const float4*)(bias + j0t + jb);
    float bz[4] = {bv.x, bv.y, bv.z, bv.w};
    float* outp = g_xw + (size_t)t * G4 * BATCH;
    #pragma unroll
    for (int j = 0; j < 4; j++) {
        float4 o = make_float4(acc[0][j] + bz[j], acc[1][j] + bz[j],
                               acc[2][j] + bz[j], acc[3][j] + bz[j]);
        *(float4*)(outp + (size_t)(j0t + jb + j) * BATCH + bb) = o;
    }
}

// ---------------- phase 2: persistent recurrent kernel -------------------------
// 128 CTAs x 256 threads. CTA owns hidden units [4*cta, 4*cta+4) -> 16 gate cols.
// SMEM floats: h 16384 + U 8192 + partials 4096 + xw 512 + c 128 + hloc 128
#define REC_SMEM_FLOATS (16384 + 8192 + 4096 + 512 + 128 + 128)
#define REC_SMEM_BYTES  (REC_SMEM_FLOATS * 4)

__device__ __forceinline__ float sigmoidf_(float v) {
    return 1.f / (1.f + __expf(-v));
}

__global__ __launch_bounds__(256) void lstm_rec_kernel(
    const float* __restrict__ U, float* __restrict__ out, int write_tail)
{
    extern __shared__ float sm[];
    float* h_sm  = sm;                      // [512][32]
    float* u_sm  = h_sm + HID * BATCH;      // [16][512]
    float* p_sm  = u_sm + 16 * HID;         // [8][16][32]
    float* xw_sm = p_sm + 8 * 16 * 32;      // [16][32]
    float* c_sm  = xw_sm + 16 * 32;         // [4][32]
    float* h_loc = c_sm + 4 * 32;           // [4][32]

    const int tid = threadIdx.x;
    const int cta = blockIdx.x;             // 0..127
    const int u0  = cta * 4;

    // load this CTA's U slice once: u_sm[c][k], c = u*4+gate -> gcol = u0+u+512*gate
    for (int i = tid; i < 16 * HID; i += 256) {
        int c = i >> 9, k = i & 511;
        int gcol = u0 + (c >> 2) + 512 * (c & 3);
        u_sm[c * 512 + k] = U[(size_t)k * G4 + gcol];
    }
    if (tid < 128) c_sm[tid] = 0.f;

    // compute-phase thread mapping
    const int ks   = tid & 7;               // K-slice 0..7
    const int tile = tid >> 3;              // 0..31
    const int tb   = tile & 7;
    const int tc   = tile >> 3;             // 0..3 (== unit index)
    const int b0   = 4 * ((tb + ks) & 7);   // rotated batch base (bank spread)
    const int c0   = 4 * tc;
    // reduce-phase mapping (tid < 128)
    const int ru = tid >> 5, rb = tid & 31;

    __syncthreads();

    for (int t = 0; t < T_STEPS; t++) {
        const int R = t & 1;
        const int Wb = R ^ 1;

        // issue xw loads early (DRAM latency hidden behind compute)
        const float* xwg = g_xw + (size_t)t * G4 * BATCH;
        float xwr[2];
        #pragma unroll
        for (int r = 0; r < 2; r++) {
            int i = tid + 256 * r;
            int c = i >> 5, b = i & 31;
            xwr[r] = xwg[(size_t)(u0 + (c >> 2) + 512 * (c & 3)) * BATCH + b];
        }

        // stage h (from L2 ping-pong buffer)
        {
            const float4* hg4 = (const float4*)g_h[R];
            float4* hs4 = (float4*)h_sm;
            #pragma unroll
            for (int r = 0; r < 16; r++)
                hs4[tid + 256 * r] = hg4[tid + 256 * r];
        }
        __syncthreads();   // A

        // partial dot products: acc[c][b] over this thread's K slice
        float acc[4][4] = {};
        #pragma unroll
        for (int jj = 0; jj < 16; jj++) {
            const int kb = 4 * ks + 32 * jj;   // k-interleave: conflict-free U loads
            float hb[4][4];
            #pragma unroll
            for (int kk = 0; kk < 4; kk++) {
                float4 hv = *(const float4*)&h_sm[(kb + kk) * 32 + b0];
                hb[kk][0] = hv.x; hb[kk][1] = hv.y; hb[kk][2] = hv.z; hb[kk][3] = hv.w;
            }
            #pragma unroll
            for (int c = 0; c < 4; c++) {
                float4 uv = *(const float4*)&u_sm[(c0 + c) * 512 + kb];
                float uk[4] = {uv.x, uv.y, uv.z, uv.w};
                #pragma unroll
                for (int kk = 0; kk < 4; kk++)
                    #pragma unroll
                    for (int b = 0; b < 4; b++)
                        acc[c][b] += uk[kk] * hb[kk][b];
            }
        }
        // write partials
        #pragma unroll
        for (int c = 0; c < 4; c++) {
            *(float4*)&p_sm[(ks * 16 + c0 + c) * 32 + b0] =
                make_float4(acc[c][0], acc[c][1], acc[c][2], acc[c][3]);
        }
        // land the xw registers
        xw_sm[tid]       = xwr[0];
        xw_sm[tid + 256] = xwr[1];
        __syncthreads();   // B

        // reduce + activations: thread (ru, rb) handles unit ru, batch rb
        if (tid < 128) {
            float s[4];
            #pragma unroll
            for (int gate = 0; gate < 4; gate++) {
                int c = ru * 4 + gate;
                float v = xw_sm[c * 32 + rb];
                #pragma unroll
                for (int k = 0; k < 8; k++)
                    v += p_sm[(k * 16 + c) * 32 + rb];
                s[gate] = v;
            }
            float ig = sigmoidf_(s[0]);
            float fg = sigmoidf_(s[1]);
            float gg = tanhf(s[2]);
            float og = sigmoidf_(s[3]);
            float cold = c_sm[ru * 32 + rb];
            float cnew = fg * cold + ig * gg;
            float hnew = og * tanhf(cnew);
            c_sm[ru * 32 + rb]  = cnew;
            h_loc[ru * 32 + rb] = hnew;
            g_h[Wb][(u0 + ru) * 32 + rb] = hnew;   // coalesced [k][b]
            if (write_tail && t == T_STEPS - 1) {
                out[(size_t)T_STEPS * BATCH * HID + (size_t)rb * HID + u0 + ru] = hnew;
                out[(size_t)T_STEPS * BATCH * HID + BATCH * HID
                    + (size_t)rb * HID + u0 + ru] = cnew;
            }
        }
        __syncthreads();   // C

        // hidden_seq: out[t][b][u0..u0+3] as one float4 per batch
        if (tid < 32) {
            float4 o4 = make_float4(h_loc[0 * 32 + tid], h_loc[1 * 32 + tid],
                                    h_loc[2 * 32 + tid], h_loc[3 * 32 + tid]);
            *(float4*)(out + (size_t)t * BATCH * HID + (size_t)tid * HID + u0) = o4;
        }
        __syncthreads();   // D (all CTA work done before release)

        // grid barrier (skip after last step)
        if (t + 1 < T_STEPS) {
            if (tid == 0) {
                unsigned int target = 128u * (unsigned int)(t + 1);
                asm volatile("red.release.gpu.add.u32 [%0], %1;"
                             :: "l"(&g_bar), "r"(1u) : "memory");
                unsigned int v;
                do {
                    asm volatile("ld.acquire.gpu.u32 %0, [%1];"
                                 : "=r"(v) : "l"(&g_bar) : "memory");
                } while (v < target);
            }
            __syncthreads();
        }
    }
}

// ---------------- launch --------------------------------------------------------
extern "C" void kernel_launch(void* const* d_in, const int* in_sizes, int n_in,
                              void* d_out, int out_size)
{
    const float* x    = (const float*)d_in[0]; // (T,B,I)
    const float* W    = (const float*)d_in[1]; // (I,4H)
    const float* U    = (const float*)d_in[2]; // (H,4H)
    const float* bias = (const float*)d_in[3]; // (4H,)
    float* out = (float*)d_out;

    const long long need_tail = (long long)T_STEPS * BATCH * HID + 2LL * BATCH * HID;
    int write_tail = ((long long)out_size >= need_tail) ? 1 : 0;

    static int configured = 0;
    if (!configured) {
        cudaFuncSetAttribute(lstm_rec_kernel,
                             cudaFuncAttributeMaxDynamicSharedMemorySize,
                             REC_SMEM_BYTES);
        configured = 1;
    }

    lstm_init_kernel<<<64, 256>>>();
    xw_gemm_kernel<<<dim3(16, T_STEPS), 256>>>(x, W, bias);
    lstm_rec_kernel<<<128, 256, REC_SMEM_BYTES>>>(U, out, write_tail);
}

// round 3
// speedup vs baseline: 1.2466x; 1.2466x over previous
#include <cuda_runtime.h>
#include <cuda_bf16.h>
#include <math.h>
#include <stdint.h>

#define T_STEPS 1024
#define BATCH   32
#define INP     512
#define HID     512
#define G4      2048   // 4*HID
#define MTOT    (T_STEPS * BATCH)   // 32768

// ---------------- scratch ----------------
__device__ float g_xw[(size_t)T_STEPS * G4 * BATCH]; // [t][col][b]  (256 MB)
__device__ __nv_bfloat16 g_xhi[(size_t)MTOT * INP];  // x hi  [m][k]
__device__ __nv_bfloat16 g_xlo[(size_t)MTOT * INP];  // x lo
__device__ __nv_bfloat16 g_whi[(size_t)G4 * INP];    // W^T hi [n][k]
__device__ __nv_bfloat16 g_wlo[(size_t)G4 * INP];    // W^T lo
__device__ float g_h[2][HID * BATCH];                // ping-pong h [k][b]
__device__ unsigned int g_bar;                       // grid barrier

// ================= helpers =================
__device__ __forceinline__ uint32_t smem_to_u32(const void* p) {
    uint32_t a;
    asm("{ .reg .u64 t; cvta.to.shared.u64 t, %1; cvt.u32.u64 %0, t; }"
        : "=r"(a) : "l"(p));
    return a;
}
#define SMEM_SWIZZLE_128B(off) ((off) ^ (((off) >> 3) & 0x70))

__device__ __forceinline__ void cp_async16(uint32_t smem_addr, const void* gptr) {
    asm volatile("cp.async.cg.shared.global [%0], [%1], 16;"
                 :: "r"(smem_addr), "l"(gptr) : "memory");
}
__device__ __forceinline__ void cp_async_commit() {
    asm volatile("cp.async.commit_group;" ::: "memory");
}
template <int N>
__device__ __forceinline__ void cp_async_wait() {
    asm volatile("cp.async.wait_group %0;" :: "n"(N) : "memory");
}

__device__ __forceinline__ void ldmatrix_x4(uint32_t* r, uint32_t addr) {
    asm volatile("ldmatrix.sync.aligned.m8n8.x4.shared.b16 {%0,%1,%2,%3}, [%4];"
                 : "=r"(r[0]), "=r"(r[1]), "=r"(r[2]), "=r"(r[3]) : "r"(addr));
}
__device__ __forceinline__ void mma_bf16(float* c, const uint32_t* a, const uint32_t* b) {
    asm volatile(
        "mma.sync.aligned.m16n8k16.row.col.f32.bf16.bf16.f32 "
        "{%0,%1,%2,%3}, {%4,%5,%6,%7}, {%8,%9}, {%0,%1,%2,%3};"
        : "+f"(c[0]), "+f"(c[1]), "+f"(c[2]), "+f"(c[3])
        : "r"(a[0]), "r"(a[1]), "r"(a[2]), "r"(a[3]), "r"(b[0]), "r"(b[1]));
}

// ---------------- init ----------------
__global__ void lstm_init_kernel() {
    int idx = blockIdx.x * blockDim.x + threadIdx.x;
    int n = 2 * HID * BATCH;
    for (int i = idx; i < n; i += gridDim.x * blockDim.x)
        ((float*)g_h)[i] = 0.f;
    if (idx == 0) g_bar = 0u;
}

// ---------------- convert x -> bf16 hi/lo ----------------
__global__ __launch_bounds__(256) void xcvt_kernel(const float* __restrict__ x) {
    size_t i = ((size_t)blockIdx.x * 256 + threadIdx.x) * 4;
    float4 v = *(const float4*)(x + i);
    __nv_bfloat16 h0 = __float2bfloat16(v.x), h1 = __float2bfloat16(v.y),
                  h2 = __float2bfloat16(v.z), h3 = __float2bfloat16(v.w);
    __nv_bfloat16 l0 = __float2bfloat16(v.x - __bfloat162float(h0));
    __nv_bfloat16 l1 = __float2bfloat16(v.y - __bfloat162float(h1));
    __nv_bfloat16 l2 = __float2bfloat16(v.z - __bfloat162float(h2));
    __nv_bfloat16 l3 = __float2bfloat16(v.w - __bfloat162float(h3));
    __nv_bfloat162* ph = (__nv_bfloat162*)(g_xhi + i);
    __nv_bfloat162* pl = (__nv_bfloat162*)(g_xlo + i);
    ph[0] = __nv_bfloat162(h0, h1); ph[1] = __nv_bfloat162(h2, h3);
    pl[0] = __nv_bfloat162(l0, l1); pl[1] = __nv_bfloat162(l2, l3);
}

// ---------------- convert + transpose W -> [n][k] bf16 hi/lo ----------------
__global__ __launch_bounds__(256) void wcvt_kernel(const float* __restrict__ W) {
    __shared__ float tile[32][33];
    int n0 = blockIdx.x * 32, k0 = blockIdx.y * 32;
    int tx = threadIdx.x & 31, ty = threadIdx.x >> 5;   // 32 x 8
    #pragma unroll
    for (int r = 0; r < 4; r++)
        tile[ty + 8 * r][tx] = W[(size_t)(k0 + ty + 8 * r) * G4 + n0 + tx];
    __syncthreads();
    #pragma unroll
    for (int r = 0; r < 4; r++) {
        float v = tile[tx][ty + 8 * r];
        __nv_bfloat16 hi = __float2bfloat16(v);
        __nv_bfloat16 lo = __float2bfloat16(v - __bfloat162float(hi));
        size_t o = (size_t)(n0 + ty + 8 * r) * INP + k0 + tx;
        g_whi[o] = hi;
        g_wlo[o] = lo;
    }
}

// ---------------- phase 1: mma.sync bf16 hi/lo GEMM ----------------
// CTA 256 thr / 8 warps. Tile M=128 x N=128, K chunks of 64, double-buffered.
// smem: [0..512) bias, [1024..) 2 x 64KB chunk buffers (Ahi|Alo|Bhi|Blo 16KB each)
// epilogue reuses buffers as Cs[128][129] float.
#define GEMM_SMEM_BYTES (1024 + 2 * 65536)

__global__ __launch_bounds__(256, 1) void xw_tc_kernel(const float* __restrict__ bias)
{
    extern __shared__ char smem[];
    const uint32_t sb = smem_to_u32(smem);
    const int tid  = threadIdx.x;
    const int wid  = tid >> 5;
    const int lane = tid & 31;
    const int n0 = blockIdx.x * 128;
    const int m0 = blockIdx.y * 128;
    float* bias_sm = (float*)smem;

    if (tid < 128) bias_sm[tid] = bias[n0 + tid];

    // warp tile: M 64 x N 32
    const int wm = (wid & 1) * 64;
    const int wn = (wid >> 1) * 32;

    // ldmatrix per-lane address parts (tile-relative bytes, pre-swizzle)
    const uint32_t aRow = (uint32_t)(lane & 15);
    const uint32_t aCol = (uint32_t)(((lane >> 4) & 1) * 16);
    const uint32_t bRow = (uint32_t)(((lane >> 4) & 1) * 8 + (lane & 7));
    const uint32_t bCol = (uint32_t)(((lane >> 3) & 1) * 16);

    uint32_t aOff[4], bOff[2];
    #pragma unroll
    for (int im = 0; im < 4; im++)
        aOff[im] = (uint32_t)(wm + 16 * im + aRow) * 128 + aCol;
    #pragma unroll
    for (int in_ = 0; in_ < 2; in_++)
        bOff[in_] = (uint32_t)(wn + 16 * in_ + bRow) * 128 + bCol;

    float c[4][4][4];
    #pragma unroll
    for (int i = 0; i < 4; i++)
        #pragma unroll
        for (int j = 0; j < 4; j++)
            #pragma unroll
            for (int k = 0; k < 4; k++) c[i][j][k] = 0.f;

    // cp.async load thread mapping: per array, 1024 16B ops, 4 per thread
    const int lrow0 = tid >> 3;          // +128 per iteration... (idx>>3)
    const int lc16  = tid & 7;

    auto issue_chunk = [&](int ch, int buf) {
        const uint32_t bbase = 1024u + (uint32_t)buf * 65536u;
        const int kb = ch * 64;
        #pragma unroll
        for (int it = 0; it < 4; it++) {
            int row = lrow0 + it * 32;
            uint32_t sw = SMEM_SWIZZLE_128B((uint32_t)(row * 128 + lc16 * 16));
            const __nv_bfloat16* gA = g_xhi + (size_t)(m0 + row) * INP + kb + lc16 * 8;
            const __nv_bfloat16* gAl= g_xlo + (size_t)(m0 + row) * INP + kb + lc16 * 8;
            const __nv_bfloat16* gB = g_whi + (size_t)(n0 + row) * INP + kb + lc16 * 8;
            const __nv_bfloat16* gBl= g_wlo + (size_t)(n0 + row) * INP + kb + lc16 * 8;
            cp_async16(sb + bbase +         sw, gA);
            cp_async16(sb + bbase + 16384 + sw, gAl);
            cp_async16(sb + bbase + 32768 + sw, gB);
            cp_async16(sb + bbase + 49152 + sw, gBl);
        }
        cp_async_commit();
    };

    issue_chunk(0, 0);

    for (int ch = 0; ch < 8; ch++) {
        const int buf = ch & 1;
        if (ch < 7) issue_chunk(ch + 1, buf ^ 1);
        if (ch < 7) cp_async_wait<1>(); else cp_async_wait<0>();
        __syncthreads();

        const uint32_t bbase = sb + 1024u + (uint32_t)buf * 65536u;
        #pragma unroll
        for (int ks = 0; ks < 4; ks++) {
            uint32_t ahi[4][4], alo[4][4], bhi[4][4], blo[4][4];
            #pragma unroll
            for (int im = 0; im < 4; im++) {
                uint32_t sw = SMEM_SWIZZLE_128B(aOff[im] + ks * 32);
                ldmatrix_x4(ahi[im], bbase + sw);
                ldmatrix_x4(alo[im], bbase + 16384 + sw);
            }
            #pragma unroll
            for (int ib = 0; ib < 2; ib++) {
                uint32_t sw = SMEM_SWIZZLE_128B(bOff[ib] + ks * 32);
                ldmatrix_x4(bhi[ib], bbase + 32768 + sw);
                ldmatrix_x4(blo[ib], bbase + 49152 + sw);
            }
            // bhi[ib] regs {0,1} = n-tile 2*ib, {2,3} = n-tile 2*ib+1
            #pragma unroll
            for (int im = 0; im < 4; im++) {
                #pragma unroll
                for (int jn = 0; jn < 4; jn++) {
                    uint32_t* bh = &bhi[jn >> 1][(jn & 1) * 2];
                    uint32_t* bl = &blo[jn >> 1][(jn & 1) * 2];
                    mma_bf16(c[im][jn], ahi[im], bh);
                    mma_bf16(c[im][jn], ahi[im], bl);
                    mma_bf16(c[im][jn], alo[im], bh);
                }
            }
        }
        __syncthreads();
    }

    // ---- epilogue: stage C in smem, then coalesced writes ----
    float* cs = (float*)(smem + 1024);   // [128][129]
    const int crow = lane >> 2;
    const int ccol = (lane & 3) * 2;
    #pragma unroll
    for (int im = 0; im < 4; im++) {
        #pragma unroll
        for (int jn = 0; jn < 4; jn++) {
            int r0 = wm + 16 * im + crow;
            int cc = wn + 8 * jn + ccol;
            cs[r0 * 129 + cc]           = c[im][jn][0];
            cs[r0 * 129 + cc + 1]       = c[im][jn][1];
            cs[(r0 + 8) * 129 + cc]     = c[im][jn][2];
            cs[(r0 + 8) * 129 + cc + 1] = c[im][jn][3];
        }
    }
    __syncthreads();

    // 512 output rows: ro = tl*128 + n ; write g_xw[(t0+tl)][n0+n][b]
    const int t0 = blockIdx.y * 4;
    for (int i = 0; i < 64; i++) {
        int ro = wid * 64 + i;
        int tl = ro >> 7, n = ro & 127;
        float v = cs[(tl * 32 + lane) * 129 + n] + bias_sm[n];
        g_xw[((size_t)(t0 + tl) * G4 + n0 + n) * BATCH + lane] = v;
    }
}

// ---------------- phase 2: persistent recurrent kernel (unchanged) ------------
#define REC_SMEM_FLOATS (16384 + 8192 + 4096 + 512 + 128 + 128)
#define REC_SMEM_BYTES  (REC_SMEM_FLOATS * 4)

__device__ __forceinline__ float sigmoidf_(float v) {
    return 1.f / (1.f + __expf(-v));
}

__global__ __launch_bounds__(256) void lstm_rec_kernel(
    const float* __restrict__ U, float* __restrict__ out, int write_tail)
{
    extern __shared__ float sm[];
    float* h_sm  = sm;                      // [512][32]
    float* u_sm  = h_sm + HID * BATCH;      // [16][512]
    float* p_sm  = u_sm + 16 * HID;         // [8][16][32]
    float* xw_sm = p_sm + 8 * 16 * 32;      // [16][32]
    float* c_sm  = xw_sm + 16 * 32;         // [4][32]
    float* h_loc = c_sm + 4 * 32;           // [4][32]

    const int tid = threadIdx.x;
    const int cta = blockIdx.x;             // 0..127
    const int u0  = cta * 4;

    for (int i = tid; i < 16 * HID; i += 256) {
        int c = i >> 9, k = i & 511;
        int gcol = u0 + (c >> 2) + 512 * (c & 3);
        u_sm[c * 512 + k] = U[(size_t)k * G4 + gcol];
    }
    if (tid < 128) c_sm[tid] = 0.f;

    const int ks   = tid & 7;
    const int tile = tid >> 3;
    const int tb   = tile & 7;
    const int tc   = tile >> 3;
    const int b0   = 4 * ((tb + ks) & 7);
    const int c0   = 4 * tc;
    const int ru = tid >> 5, rb = tid & 31;

    __syncthreads();

    for (int t = 0; t < T_STEPS; t++) {
        const int R = t & 1;
        const int Wb = R ^ 1;

        const float* xwg = g_xw + (size_t)t * G4 * BATCH;
        float xwr[2];
        #pragma unroll
        for (int r = 0; r < 2; r++) {
            int i = tid + 256 * r;
            int c = i >> 5, b = i & 31;
            xwr[r] = xwg[(size_t)(u0 + (c >> 2) + 512 * (c & 3)) * BATCH + b];
        }

        {
            const float4* hg4 = (const float4*)g_h[R];
            float4* hs4 = (float4*)h_sm;
            #pragma unroll
            for (int r = 0; r < 16; r++)
                hs4[tid + 256 * r] = hg4[tid + 256 * r];
        }
        __syncthreads();   // A

        float acc[4][4] = {};
        #pragma unroll
        for (int jj = 0; jj < 16; jj++) {
            const int kb = 4 * ks + 32 * jj;
            float hb[4][4];
            #pragma unroll
            for (int kk = 0; kk < 4; kk++) {
                float4 hv = *(const float4*)&h_sm[(kb + kk) * 32 + b0];
                hb[kk][0] = hv.x; hb[kk][1] = hv.y; hb[kk][2] = hv.z; hb[kk][3] = hv.w;
            }
            #pragma unroll
            for (int c = 0; c < 4; c++) {
                float4 uv = *(const float4*)&u_sm[(c0 + c) * 512 + kb];
                float uk[4] = {uv.x, uv.y, uv.z, uv.w};
                #pragma unroll
                for (int kk = 0; kk < 4; kk++)
                    #pragma unroll
                    for (int b = 0; b < 4; b++)
                        acc[c][b] += uk[kk] * hb[kk][b];
            }
        }
        #pragma unroll
        for (int c = 0; c < 4; c++) {
            *(float4*)&p_sm[(ks * 16 + c0 + c) * 32 + b0] =
                make_float4(acc[c][0], acc[c][1], acc[c][2], acc[c][3]);
        }
        xw_sm[tid]       = xwr[0];
        xw_sm[tid + 256] = xwr[1];
        __syncthreads();   // B

        if (tid < 128) {
            float s[4];
            #pragma unroll
            for (int gate = 0; gate < 4; gate++) {
                int c = ru * 4 + gate;
                float v = xw_sm[c * 32 + rb];
                #pragma unroll
                for (int k = 0; k < 8; k++)
                    v += p_sm[(k * 16 + c) * 32 + rb];
                s[gate] = v;
            }
            float ig = sigmoidf_(s[0]);
            float fg = sigmoidf_(s[1]);
            float gg = tanhf(s[2]);
            float og = sigmoidf_(s[3]);
            float cold = c_sm[ru * 32 + rb];
            float cnew = fg * cold + ig * gg;
            float hnew = og * tanhf(cnew);
            c_sm[ru * 32 + rb]  = cnew;
            h_loc[ru * 32 + rb] = hnew;
            g_h[Wb][(u0 + ru) * 32 + rb] = hnew;
            if (write_tail && t == T_STEPS - 1) {
                out[(size_t)T_STEPS * BATCH * HID + (size_t)rb * HID + u0 + ru] = hnew;
                out[(size_t)T_STEPS * BATCH * HID + BATCH * HID
                    + (size_t)rb * HID + u0 + ru] = cnew;
            }
        }
        __syncthreads();   // C

        if (tid < 32) {
            float4 o4 = make_float4(h_loc[0 * 32 + tid], h_loc[1 * 32 + tid],
                                    h_loc[2 * 32 + tid], h_loc[3 * 32 + tid]);
            *(float4*)(out + (size_t)t * BATCH * HID + (size_t)tid * HID + u0) = o4;
        }
        __syncthreads();   // D

        if (t + 1 < T_STEPS) {
            if (tid == 0) {
                unsigned int target = 128u * (unsigned int)(t + 1);
                asm volatile("red.release.gpu.add.u32 [%0], %1;"
                             :: "l"(&g_bar), "r"(1u) : "memory");
                unsigned int v;
                do {
                    asm volatile("ld.acquire.gpu.u32 %0, [%1];"
                                 : "=r"(v) : "l"(&g_bar) : "memory");
                } while (v < target);
            }
            __syncthreads();
        }
    }
}

// ---------------- launch ----------------
extern "C" void kernel_launch(void* const* d_in, const int* in_sizes, int n_in,
                              void* d_out, int out_size)
{
    const float* x    = (const float*)d_in[0]; // (T,B,I)
    const float* W    = (const float*)d_in[1]; // (I,4H)
    const float* U    = (const float*)d_in[2]; // (H,4H)
    const float* bias = (const float*)d_in[3]; // (4H,)
    float* out = (float*)d_out;

    const long long need_tail = (long long)T_STEPS * BATCH * HID + 2LL * BATCH * HID;
    int write_tail = ((long long)out_size >= need_tail) ? 1 : 0;

    static int configured = 0;
    if (!configured) {
        cudaFuncSetAttribute(lstm_rec_kernel,
                             cudaFuncAttributeMaxDynamicSharedMemorySize,
                             REC_SMEM_BYTES);
        cudaFuncSetAttribute(xw_tc_kernel,
                             cudaFuncAttributeMaxDynamicSharedMemorySize,
                             GEMM_SMEM_BYTES);
        configured = 1;
    }

    lstm_init_kernel<<<64, 256>>>();
    xcvt_kernel<<<(MTOT * INP) / 4 / 256, 256>>>(x);
    wcvt_kernel<<<dim3(G4 / 32, INP / 32), 256>>>(W);
    xw_tc_kernel<<<dim3(16, 256), 256, GEMM_SMEM_BYTES>>>(bias);
    lstm_rec_kernel<<<128, 256, REC_SMEM_BYTES>>>(U, out, write_tail);
}

// round 5
// speedup vs baseline: 1.5118x; 1.2127x over previous
#include <cuda_runtime.h>
#include <cuda_bf16.h>
#include <math.h>
#include <stdint.h>

#define T_STEPS 1024
#define BATCH   32
#define INP     512
#define HID     512
#define G4      2048   // 4*HID
#define MTOT    (T_STEPS * BATCH)   // 32768

// ---------------- scratch ----------------
__device__ float g_xw[(size_t)T_STEPS * G4 * BATCH]; // [t][col][b]  (256 MB)
__device__ __nv_bfloat16 g_xhi[(size_t)MTOT * INP];  // x hi  [m][k]
__device__ __nv_bfloat16 g_xlo[(size_t)MTOT * INP];  // x lo
__device__ __nv_bfloat16 g_whi[(size_t)G4 * INP];    // W^T hi [n][k]
__device__ __nv_bfloat16 g_wlo[(size_t)G4 * INP];    // W^T lo
__device__ __nv_bfloat16 g_hb[2][2][BATCH * HID];    // h ping-pong [ping][hi/lo][b*512+k]
__device__ unsigned int g_bar;                       // grid barrier

// ================= helpers =================
__device__ __forceinline__ uint32_t smem_to_u32(const void* p) {
    uint32_t a;
    asm("{ .reg .u64 t; cvta.to.shared.u64 t, %1; cvt.u32.u64 %0, t; }"
        : "=r"(a) : "l"(p));
    return a;
}
#define SMEM_SWIZZLE_128B(off) ((off) ^ (((off) >> 3) & 0x70))

__device__ __forceinline__ void cp_async16(uint32_t smem_addr, const void* gptr) {
    asm volatile("cp.async.cg.shared.global [%0], [%1], 16;"
                 :: "r"(smem_addr), "l"(gptr) : "memory");
}
__device__ __forceinline__ void cp_async_commit() {
    asm volatile("cp.async.commit_group;" ::: "memory");
}
template <int N>
__device__ __forceinline__ void cp_async_wait() {
    asm volatile("cp.async.wait_group %0;" :: "n"(N) : "memory");
}

__device__ __forceinline__ void ldmatrix_x4(uint32_t* r, uint32_t addr) {
    asm volatile("ldmatrix.sync.aligned.m8n8.x4.shared.b16 {%0,%1,%2,%3}, [%4];"
                 : "=r"(r[0]), "=r"(r[1]), "=r"(r[2]), "=r"(r[3]) : "r"(addr));
}
__device__ __forceinline__ void mma_bf16(float* c, const uint32_t* a, const uint32_t* b) {
    asm volatile(
        "mma.sync.aligned.m16n8k16.row.col.f32.bf16.bf16.f32 "
        "{%0,%1,%2,%3}, {%4,%5,%6,%7}, {%8,%9}, {%0,%1,%2,%3};"
        : "+f"(c[0]), "+f"(c[1]), "+f"(c[2]), "+f"(c[3])
        : "r"(a[0]), "r"(a[1]), "r"(a[2]), "r"(a[3]), "r"(b[0]), "r"(b[1]));
}
__device__ __forceinline__ float sigmoidf_(float v) {
    return 1.f / (1.f + __expf(-v));
}

// ---------------- init ----------------
__global__ void lstm_init_kernel() {
    int idx = blockIdx.x * blockDim.x + threadIdx.x;
    int n = 2 * 2 * BATCH * HID;
    __nv_bfloat16 z = __float2bfloat16(0.f);
    for (int i = idx; i < n; i += gridDim.x * blockDim.x)
        ((__nv_bfloat16*)g_hb)[i] = z;
    if (idx == 0) g_bar = 0u;
}

// ---------------- convert x -> bf16 hi/lo ----------------
__global__ __launch_bounds__(256) void xcvt_kernel(const float* __restrict__ x) {
    size_t i = ((size_t)blockIdx.x * 256 + threadIdx.x) * 4;
    float4 v = *(const float4*)(x + i);
    __nv_bfloat16 h0 = __float2bfloat16(v.x), h1 = __float2bfloat16(v.y),
                  h2 = __float2bfloat16(v.z), h3 = __float2bfloat16(v.w);
    __nv_bfloat16 l0 = __float2bfloat16(v.x - __bfloat162float(h0));
    __nv_bfloat16 l1 = __float2bfloat16(v.y - __bfloat162float(h1));
    __nv_bfloat16 l2 = __float2bfloat16(v.z - __bfloat162float(h2));
    __nv_bfloat16 l3 = __float2bfloat16(v.w - __bfloat162float(h3));
    __nv_bfloat162* ph = (__nv_bfloat162*)(g_xhi + i);
    __nv_bfloat162* pl = (__nv_bfloat162*)(g_xlo + i);
    ph[0] = __nv_bfloat162(h0, h1); ph[1] = __nv_bfloat162(h2, h3);
    pl[0] = __nv_bfloat162(l0, l1); pl[1] = __nv_bfloat162(l2, l3);
}

// ---------------- convert + transpose W -> [n][k] bf16 hi/lo ----------------
__global__ __launch_bounds__(256) void wcvt_kernel(const float* __restrict__ W) {
    __shared__ float tile[32][33];
    int n0 = blockIdx.x * 32, k0 = blockIdx.y * 32;
    int tx = threadIdx.x & 31, ty = threadIdx.x >> 5;   // 32 x 8
    #pragma unroll
    for (int r = 0; r < 4; r++)
        tile[ty + 8 * r][tx] = W[(size_t)(k0 + ty + 8 * r) * G4 + n0 + tx];
    __syncthreads();
    #pragma unroll
    for (int r = 0; r < 4; r++) {
        float v = tile[tx][ty + 8 * r];
        __nv_bfloat16 hi = __float2bfloat16(v);
        __nv_bfloat16 lo = __float2bfloat16(v - __bfloat162float(hi));
        size_t o = (size_t)(n0 + ty + 8 * r) * INP + k0 + tx;
        g_whi[o] = hi;
        g_wlo[o] = lo;
    }
}

// ---------------- phase 1: mma.sync bf16 hi/lo GEMM (unchanged) ----------------
#define GEMM_SMEM_BYTES (1024 + 2 * 65536)

__global__ __launch_bounds__(256, 1) void xw_tc_kernel(const float* __restrict__ bias)
{
    extern __shared__ char smem[];
    const uint32_t sb = smem_to_u32(smem);
    const int tid  = threadIdx.x;
    const int wid  = tid >> 5;
    const int lane = tid & 31;
    const int n0 = blockIdx.x * 128;
    const int m0 = blockIdx.y * 128;
    float* bias_sm = (float*)smem;

    if (tid < 128) bias_sm[tid] = bias[n0 + tid];

    const int wm = (wid & 1) * 64;
    const int wn = (wid >> 1) * 32;

    const uint32_t aRow = (uint32_t)(lane & 15);
    const uint32_t aCol = (uint32_t)(((lane >> 4) & 1) * 16);
    const uint32_t bRow = (uint32_t)(((lane >> 4) & 1) * 8 + (lane & 7));
    const uint32_t bCol = (uint32_t)(((lane >> 3) & 1) * 16);

    uint32_t aOff[4], bOff[2];
    #pragma unroll
    for (int im = 0; im < 4; im++)
        aOff[im] = (uint32_t)(wm + 16 * im + aRow) * 128 + aCol;
    #pragma unroll
    for (int in_ = 0; in_ < 2; in_++)
        bOff[in_] = (uint32_t)(wn + 16 * in_ + bRow) * 128 + bCol;

    float c[4][4][4];
    #pragma unroll
    for (int i = 0; i < 4; i++)
        #pragma unroll
        for (int j = 0; j < 4; j++)
            #pragma unroll
            for (int k = 0; k < 4; k++) c[i][j][k] = 0.f;

    const int lrow0 = tid >> 3;
    const int lc16  = tid & 7;

    auto issue_chunk = [&](int ch, int buf) {
        const uint32_t bbase = 1024u + (uint32_t)buf * 65536u;
        const int kb = ch * 64;
        #pragma unroll
        for (int it = 0; it < 4; it++) {
            int row = lrow0 + it * 32;
            uint32_t sw = SMEM_SWIZZLE_128B((uint32_t)(row * 128 + lc16 * 16));
            const __nv_bfloat16* gA = g_xhi + (size_t)(m0 + row) * INP + kb + lc16 * 8;
            const __nv_bfloat16* gAl= g_xlo + (size_t)(m0 + row) * INP + kb + lc16 * 8;
            const __nv_bfloat16* gB = g_whi + (size_t)(n0 + row) * INP + kb + lc16 * 8;
            const __nv_bfloat16* gBl= g_wlo + (size_t)(n0 + row) * INP + kb + lc16 * 8;
            cp_async16(sb + bbase +         sw, gA);
            cp_async16(sb + bbase + 16384 + sw, gAl);
            cp_async16(sb + bbase + 32768 + sw, gB);
            cp_async16(sb + bbase + 49152 + sw, gBl);
        }
        cp_async_commit();
    };

    issue_chunk(0, 0);

    for (int ch = 0; ch < 8; ch++) {
        const int buf = ch & 1;
        if (ch < 7) issue_chunk(ch + 1, buf ^ 1);
        if (ch < 7) cp_async_wait<1>(); else cp_async_wait<0>();
        __syncthreads();

        const uint32_t bbase = sb + 1024u + (uint32_t)buf * 65536u;
        #pragma unroll
        for (int ks = 0; ks < 4; ks++) {
            uint32_t ahi[4][4], alo[4][4], bhi[4][4], blo[4][4];
            #pragma unroll
            for (int im = 0; im < 4; im++) {
                uint32_t sw = SMEM_SWIZZLE_128B(aOff[im] + ks * 32);
                ldmatrix_x4(ahi[im], bbase + sw);
                ldmatrix_x4(alo[im], bbase + 16384 + sw);
            }
            #pragma unroll
            for (int ib = 0; ib < 2; ib++) {
                uint32_t sw = SMEM_SWIZZLE_128B(bOff[ib] + ks * 32);
                ldmatrix_x4(bhi[ib], bbase + 32768 + sw);
                ldmatrix_x4(blo[ib], bbase + 49152 + sw);
            }
            #pragma unroll
            for (int im = 0; im < 4; im++) {
                #pragma unroll
                for (int jn = 0; jn < 4; jn++) {
                    uint32_t* bh = &bhi[jn >> 1][(jn & 1) * 2];
                    uint32_t* bl = &blo[jn >> 1][(jn & 1) * 2];
                    mma_bf16(c[im][jn], ahi[im], bh);
                    mma_bf16(c[im][jn], ahi[im], bl);
                    mma_bf16(c[im][jn], alo[im], bh);
                }
            }
        }
        __syncthreads();
    }

    float* cs = (float*)(smem + 1024);   // [128][129]
    const int crow = lane >> 2;
    const int ccol = (lane & 3) * 2;
    #pragma unroll
    for (int im = 0; im < 4; im++) {
        #pragma unroll
        for (int jn = 0; jn < 4; jn++) {
            int r0 = wm + 16 * im + crow;
            int cc = wn + 8 * jn + ccol;
            cs[r0 * 129 + cc]           = c[im][jn][0];
            cs[r0 * 129 + cc + 1]       = c[im][jn][1];
            cs[(r0 + 8) * 129 + cc]     = c[im][jn][2];
            cs[(r0 + 8) * 129 + cc + 1] = c[im][jn][3];
        }
    }
    __syncthreads();

    const int t0 = blockIdx.y * 4;
    for (int i = 0; i < 64; i++) {
        int ro = wid * 64 + i;
        int tl = ro >> 7, n = ro & 127;
        float v = cs[(tl * 32 + lane) * 129 + n] + bias_sm[n];
        g_xw[((size_t)(t0 + tl) * G4 + n0 + n) * BATCH + lane] = v;
    }
}

// ---------------- phase 2: tensor-core persistent recurrence -------------------
// 64 CTAs x 128 threads. CTA owns 8 hidden units -> 32 gate cols (gate-major:
// local n = g*8+u -> global gcol = u0+u+512g).
// Warp w owns K-chunks w and w+4: issues their cp.asyncs AND consumes them
// (cp.async completion is per-thread; converged warp-level wait covers the
// warp's own loads -- never consume another warp's un-drained cp.asyncs).
// smem bytes:
//   [0      .. 32768)  h hi, 8 chunks of [32 b][64 k] bf16 (4KB each, swizzled)
//   [32768  .. 65536)  h lo
//   [65536  .. 98304)  U hi, 8 chunks of [32 n][64 k] bf16
//   [98304  ..131072)  U lo
//   [131072 ..135168)  xw  [32 n][32 b] fp32
//   [135168 ..152576)  partials [4 w][32 m][34 pad] fp32
#define R_HHI 0
#define R_HLO 32768
#define R_UHI 65536
#define R_ULO 98304
#define R_XW  131072
#define R_P   135168
#define REC2_SMEM_BYTES 152576
#define NCTA  64

__global__ __launch_bounds__(128, 1) void lstm_rec_tc_kernel(
    const float* __restrict__ U, float* __restrict__ out, int write_tail)
{
    extern __shared__ char smem[];
    const uint32_t sb = smem_to_u32(smem);
    const int tid  = threadIdx.x;
    const int wid  = tid >> 5;
    const int lane = tid & 31;
    const int u0   = blockIdx.x * 8;

    // ---- load U slice -> smem bf16 hi/lo, chunked+swizzled ----
    for (int i = tid; i < 32 * HID; i += 128) {
        int k = i >> 5, n = i & 31;
        int gcol = u0 + (n & 7) + 512 * (n >> 3);
        float v = U[(size_t)k * G4 + gcol];
        __nv_bfloat16 hi = __float2bfloat16(v);
        __nv_bfloat16 lo = __float2bfloat16(v - __bfloat162float(hi));
        int c = k >> 6, ko = k & 63;
        uint32_t sw = SMEM_SWIZZLE_128B((uint32_t)(n * 128 + ko * 2));
        *(__nv_bfloat16*)(smem + R_UHI + c * 4096 + sw) = hi;
        *(__nv_bfloat16*)(smem + R_ULO + c * 4096 + sw) = lo;
    }

    // ldmatrix lane address parts (within a [32 rows][128B] chunk)
    const uint32_t aRow = (uint32_t)(lane & 15);
    const uint32_t aCol = (uint32_t)(((lane >> 4) & 1) * 16);
    const uint32_t bRow = (uint32_t)(((lane >> 4) & 1) * 8 + (lane & 7));
    const uint32_t bCol = (uint32_t)(((lane >> 3) & 1) * 16);
    uint32_t aBase[2], bBase[2];
    #pragma unroll
    for (int mt = 0; mt < 2; mt++) aBase[mt] = (uint32_t)(mt * 16 + aRow) * 128 + aCol;
    #pragma unroll
    for (int ng = 0; ng < 2; ng++) bBase[ng] = (uint32_t)(ng * 16 + bRow) * 128 + bCol;

    // reduce-phase mapping: thread handles (b, ua) and (b, ua+1)
    const int rb = tid >> 2;
    const int ua = (tid & 3) * 2;
    float c_state[2] = {0.f, 0.f};

    float* p_sm  = (float*)(smem + R_P);
    float* xw_sm = (float*)(smem + R_XW);

    // xw prefetch for a step (1 cp.async group, all threads participate)
    auto issue_xw = [&](int t) {
        #pragma unroll
        for (int j = 0; j < 2; j++) {
            int idx = tid + 128 * j;
            int n = idx >> 3, seg = idx & 7;
            int gcol = u0 + (n & 7) + 512 * (n >> 3);
            cp_async16(sb + R_XW + (uint32_t)(n * 128 + seg * 16),
                       g_xw + ((size_t)t * G4 + gcol) * BATCH + seg * 4);
        }
        cp_async_commit();
    };
    // h chunk load: ONE WARP loads the whole chunk (its own cp.asyncs)
    auto issue_h_chunk = [&](int R, int cc) {
        const __nv_bfloat16* hhi = g_hb[R][0];
        const __nv_bfloat16* hlo = g_hb[R][1];
        #pragma unroll
        for (int j = 0; j < 8; j++) {
            int idx = lane + 32 * j;
            int b = idx >> 3, seg = idx & 7;
            uint32_t sw = SMEM_SWIZZLE_128B((uint32_t)(b * 128 + seg * 16));
            cp_async16(sb + R_HHI + cc * 4096 + sw, hhi + b * 512 + cc * 64 + seg * 8);
            cp_async16(sb + R_HLO + cc * 4096 + sw, hlo + b * 512 + cc * 64 + seg * 8);
        }
        cp_async_commit();
    };

    __syncthreads();            // U slice ready
    issue_xw(0);

    for (int t = 0; t < T_STEPS; t++) {
        const int R = t & 1;

        // warp w loads its own chunks w and w+4 (2 commit groups)
        issue_h_chunk(R, wid);
        issue_h_chunk(R, wid + 4);

        float cfr[2][4][4];
        #pragma unroll
        for (int mt = 0; mt < 2; mt++)
            #pragma unroll
            for (int jn = 0; jn < 4; jn++)
                #pragma unroll
                for (int q = 0; q < 4; q++) cfr[mt][jn][q] = 0.f;

        // pending per thread: xw(t), chunk wid, chunk wid+4
        #pragma unroll
        for (int half = 0; half < 2; half++) {
            const int cc = wid + 4 * half;
            if (half == 0) cp_async_wait<1>();   // drains xw + chunk wid
            else           cp_async_wait<0>();   // drains chunk wid+4
            const uint32_t hbse = sb + R_HHI + cc * 4096;
            const uint32_t ubse = sb + R_UHI + cc * 4096;
            #pragma unroll
            for (int kt = 0; kt < 4; kt++) {
                uint32_t ahi[2][4], alo[2][4], bhi[2][4], blo[2][4];
                #pragma unroll
                for (int mt = 0; mt < 2; mt++) {
                    uint32_t sw = SMEM_SWIZZLE_128B(aBase[mt] + kt * 32);
                    ldmatrix_x4(ahi[mt], hbse + sw);
                    ldmatrix_x4(alo[mt], hbse + 32768 + sw);
                }
                #pragma unroll
                for (int ng = 0; ng < 2; ng++) {
                    uint32_t sw = SMEM_SWIZZLE_128B(bBase[ng] + kt * 32);
                    ldmatrix_x4(bhi[ng], ubse + sw);
                    ldmatrix_x4(blo[ng], ubse + 32768 + sw);
                }
                #pragma unroll
                for (int mt = 0; mt < 2; mt++) {
                    #pragma unroll
                    for (int jn = 0; jn < 4; jn++) {
                        uint32_t* bh = &bhi[jn >> 1][(jn & 1) * 2];
                        uint32_t* bl = &blo[jn >> 1][(jn & 1) * 2];
                        mma_bf16(cfr[mt][jn], ahi[mt], bh);
                        mma_bf16(cfr[mt][jn], ahi[mt], bl);
                        mma_bf16(cfr[mt][jn], alo[mt], bh);
                    }
                }
            }
        }

        // write K-partials to smem [w][m][34]
        {
            const int m  = lane >> 2;
            const int nn = 2 * (lane & 3);
            #pragma unroll
            for (int mt = 0; mt < 2; mt++) {
                #pragma unroll
                for (int jn = 0; jn < 4; jn++) {
                    int row = wid * 32 + mt * 16 + m;
                    int col = jn * 8 + nn;
                    *(float2*)&p_sm[row * 34 + col] =
                        make_float2(cfr[mt][jn][0], cfr[mt][jn][1]);
                    *(float2*)&p_sm[(row + 8) * 34 + col] =
                        make_float2(cfr[mt][jn][2], cfr[mt][jn][3]);
                }
            }
        }
        __syncthreads();   // partials + xw visible to all threads

        // reduce + activations: this thread owns (rb, ua) and (rb, ua+1)
        #pragma unroll
        for (int ii = 0; ii < 2; ii++) {
            const int u = ua + ii;
            float s[4];
            #pragma unroll
            for (int g = 0; g < 4; g++) {
                int n = g * 8 + u;
                float v = xw_sm[n * 32 + rb];
                #pragma unroll
                for (int w = 0; w < 4; w++)
                    v += p_sm[(w * 32 + rb) * 34 + n];
                s[g] = v;
            }
            float ig = sigmoidf_(s[0]);
            float fg = sigmoidf_(s[1]);
            float gg = tanhf(s[2]);
            float og = sigmoidf_(s[3]);
            float cnew = fg * c_state[ii] + ig * gg;
            float hnew = og * tanhf(cnew);
            c_state[ii] = cnew;

            out[((size_t)t * BATCH + rb) * HID + u0 + u] = hnew;
            __nv_bfloat16 hh = __float2bfloat16(hnew);
            __nv_bfloat16 hl = __float2bfloat16(hnew - __bfloat162float(hh));
            g_hb[R ^ 1][0][rb * 512 + u0 + u] = hh;
            g_hb[R ^ 1][1][rb * 512 + u0 + u] = hl;
            if (write_tail && t == T_STEPS - 1) {
                out[(size_t)T_STEPS * BATCH * HID + (size_t)rb * HID + u0 + u] = hnew;
                out[(size_t)T_STEPS * BATCH * HID + BATCH * HID
                    + (size_t)rb * HID + u0 + u] = cnew;
            }
        }
        __syncthreads();   // all xw_sm reads done before refilling it

        // prefetch xw for next step (safe: reads finished above)
        if (t + 1 < T_STEPS) issue_xw(t + 1);

        // grid barrier
        if (t + 1 < T_STEPS) {
            if (tid == 0) {
                unsigned int target = (unsigned int)NCTA * (unsigned int)(t + 1);
                asm volatile("red.release.gpu.add.u32 [%0], %1;"
                             :: "l"(&g_bar), "r"(1u) : "memory");
                unsigned int v;
                do {
                    asm volatile("ld.acquire.gpu.u32 %0, [%1];"
                                 : "=r"(v) : "l"(&g_bar) : "memory");
                } while (v < target);
            }
            __syncthreads();
        }
    }
}

// ---------------- launch ----------------
extern "C" void kernel_launch(void* const* d_in, const int* in_sizes, int n_in,
                              void* d_out, int out_size)
{
    const float* x    = (const float*)d_in[0]; // (T,B,I)
    const float* W    = (const float*)d_in[1]; // (I,4H)
    const float* U    = (const float*)d_in[2]; // (H,4H)
    const float* bias = (const float*)d_in[3]; // (4H,)
    float* out = (float*)d_out;

    const long long need_tail = (long long)T_STEPS * BATCH * HID + 2LL * BATCH * HID;
    int write_tail = ((long long)out_size >= need_tail) ? 1 : 0;

    static int configured = 0;
    if (!configured) {
        cudaFuncSetAttribute(xw_tc_kernel,
                             cudaFuncAttributeMaxDynamicSharedMemorySize,
                             GEMM_SMEM_BYTES);
        cudaFuncSetAttribute(lstm_rec_tc_kernel,
                             cudaFuncAttributeMaxDynamicSharedMemorySize,
                             REC2_SMEM_BYTES);
        configured = 1;
    }

    lstm_init_kernel<<<64, 256>>>();
    xcvt_kernel<<<(MTOT * INP) / 4 / 256, 256>>>(x);
    wcvt_kernel<<<dim3(G4 / 32, INP / 32), 256>>>(W);
    xw_tc_kernel<<<dim3(16, 256), 256, GEMM_SMEM_BYTES>>>(bias);
    lstm_rec_tc_kernel<<<NCTA, 128, REC2_SMEM_BYTES>>>(U, out, write_tail);
}

// round 6
// speedup vs baseline: 1.9137x; 1.2659x over previous
#include <cuda_runtime.h>
#include <cuda_bf16.h>
#include <math.h>
#include <stdint.h>

#define T_STEPS 1024
#define BATCH   32
#define INP     512
#define HID     512
#define G4      2048   // 4*HID
#define MTOT    (T_STEPS * BATCH)   // 32768

// ---------------- scratch ----------------
__device__ float g_xw[(size_t)T_STEPS * G4 * BATCH]; // [t][col][b]  (256 MB)
__device__ __nv_bfloat16 g_xhi[(size_t)MTOT * INP];  // x hi  [m][k]
__device__ __nv_bfloat16 g_xlo[(size_t)MTOT * INP];  // x lo
__device__ __nv_bfloat16 g_whi[(size_t)G4 * INP];    // W^T hi [n][k]
__device__ __nv_bfloat16 g_wlo[(size_t)G4 * INP];    // W^T lo
__device__ __nv_bfloat16 g_hb[2][2][BATCH * HID];    // h ping-pong [ping][hi/lo][b*512+k]
__device__ unsigned int g_bar;                       // grid barrier

// ================= helpers =================
__device__ __forceinline__ uint32_t smem_to_u32(const void* p) {
    uint32_t a;
    asm("{ .reg .u64 t; cvta.to.shared.u64 t, %1; cvt.u32.u64 %0, t; }"
        : "=r"(a) : "l"(p));
    return a;
}
#define SMEM_SWIZZLE_128B(off) ((off) ^ (((off) >> 3) & 0x70))

__device__ __forceinline__ void cp_async16(uint32_t smem_addr, const void* gptr) {
    asm volatile("cp.async.cg.shared.global [%0], [%1], 16;"
                 :: "r"(smem_addr), "l"(gptr) : "memory");
}
__device__ __forceinline__ void cp_async_commit() {
    asm volatile("cp.async.commit_group;" ::: "memory");
}
template <int N>
__device__ __forceinline__ void cp_async_wait() {
    asm volatile("cp.async.wait_group %0;" :: "n"(N) : "memory");
}

__device__ __forceinline__ void ldmatrix_x4(uint32_t* r, uint32_t addr) {
    asm volatile("ldmatrix.sync.aligned.m8n8.x4.shared.b16 {%0,%1,%2,%3}, [%4];"
                 : "=r"(r[0]), "=r"(r[1]), "=r"(r[2]), "=r"(r[3]) : "r"(addr));
}
__device__ __forceinline__ void mma_bf16(float* c, const uint32_t* a, const uint32_t* b) {
    asm volatile(
        "mma.sync.aligned.m16n8k16.row.col.f32.bf16.bf16.f32 "
        "{%0,%1,%2,%3}, {%4,%5,%6,%7}, {%8,%9}, {%0,%1,%2,%3};"
        : "+f"(c[0]), "+f"(c[1]), "+f"(c[2]), "+f"(c[3])
        : "r"(a[0]), "r"(a[1]), "r"(a[2]), "r"(a[3]), "r"(b[0]), "r"(b[1]));
}
__device__ __forceinline__ float sigmoidf_(float v) {
    return 1.f / (1.f + __expf(-v));
}

// ---------------- init ----------------
__global__ void lstm_init_kernel() {
    int idx = blockIdx.x * blockDim.x + threadIdx.x;
    int n = 2 * 2 * BATCH * HID;
    __nv_bfloat16 z = __float2bfloat16(0.f);
    for (int i = idx; i < n; i += gridDim.x * blockDim.x)
        ((__nv_bfloat16*)g_hb)[i] = z;
    if (idx == 0) g_bar = 0u;
}

// ---------------- convert x -> bf16 hi/lo ----------------
__global__ __launch_bounds__(256) void xcvt_kernel(const float* __restrict__ x) {
    size_t i = ((size_t)blockIdx.x * 256 + threadIdx.x) * 4;
    float4 v = *(const float4*)(x + i);
    __nv_bfloat16 h0 = __float2bfloat16(v.x), h1 = __float2bfloat16(v.y),
                  h2 = __float2bfloat16(v.z), h3 = __float2bfloat16(v.w);
    __nv_bfloat16 l0 = __float2bfloat16(v.x - __bfloat162float(h0));
    __nv_bfloat16 l1 = __float2bfloat16(v.y - __bfloat162float(h1));
    __nv_bfloat16 l2 = __float2bfloat16(v.z - __bfloat162float(h2));
    __nv_bfloat16 l3 = __float2bfloat16(v.w - __bfloat162float(h3));
    __nv_bfloat162* ph = (__nv_bfloat162*)(g_xhi + i);
    __nv_bfloat162* pl = (__nv_bfloat162*)(g_xlo + i);
    ph[0] = __nv_bfloat162(h0, h1); ph[1] = __nv_bfloat162(h2, h3);
    pl[0] = __nv_bfloat162(l0, l1); pl[1] = __nv_bfloat162(l2, l3);
}

// ---------------- convert + transpose W -> [n][k] bf16 hi/lo ----------------
__global__ __launch_bounds__(256) void wcvt_kernel(const float* __restrict__ W) {
    __shared__ float tile[32][33];
    int n0 = blockIdx.x * 32, k0 = blockIdx.y * 32;
    int tx = threadIdx.x & 31, ty = threadIdx.x >> 5;   // 32 x 8
    #pragma unroll
    for (int r = 0; r < 4; r++)
        tile[ty + 8 * r][tx] = W[(size_t)(k0 + ty + 8 * r) * G4 + n0 + tx];
    __syncthreads();
    #pragma unroll
    for (int r = 0; r < 4; r++) {
        float v = tile[tx][ty + 8 * r];
        __nv_bfloat16 hi = __float2bfloat16(v);
        __nv_bfloat16 lo = __float2bfloat16(v - __bfloat162float(hi));
        size_t o = (size_t)(n0 + ty + 8 * r) * INP + k0 + tx;
        g_whi[o] = hi;
        g_wlo[o] = lo;
    }
}

// ---------------- phase 1: mma.sync bf16 hi/lo GEMM (unchanged) ----------------
#define GEMM_SMEM_BYTES (1024 + 2 * 65536)

__global__ __launch_bounds__(256, 1) void xw_tc_kernel(const float* __restrict__ bias)
{
    extern __shared__ char smem[];
    const uint32_t sb = smem_to_u32(smem);
    const int tid  = threadIdx.x;
    const int wid  = tid >> 5;
    const int lane = tid & 31;
    const int n0 = blockIdx.x * 128;
    const int m0 = blockIdx.y * 128;
    float* bias_sm = (float*)smem;

    if (tid < 128) bias_sm[tid] = bias[n0 + tid];

    const int wm = (wid & 1) * 64;
    const int wn = (wid >> 1) * 32;

    const uint32_t aRow = (uint32_t)(lane & 15);
    const uint32_t aCol = (uint32_t)(((lane >> 4) & 1) * 16);
    const uint32_t bRow = (uint32_t)(((lane >> 4) & 1) * 8 + (lane & 7));
    const uint32_t bCol = (uint32_t)(((lane >> 3) & 1) * 16);

    uint32_t aOff[4], bOff[2];
    #pragma unroll
    for (int im = 0; im < 4; im++)
        aOff[im] = (uint32_t)(wm + 16 * im + aRow) * 128 + aCol;
    #pragma unroll
    for (int in_ = 0; in_ < 2; in_++)
        bOff[in_] = (uint32_t)(wn + 16 * in_ + bRow) * 128 + bCol;

    float c[4][4][4];
    #pragma unroll
    for (int i = 0; i < 4; i++)
        #pragma unroll
        for (int j = 0; j < 4; j++)
            #pragma unroll
            for (int k = 0; k < 4; k++) c[i][j][k] = 0.f;

    const int lrow0 = tid >> 3;
    const int lc16  = tid & 7;

    auto issue_chunk = [&](int ch, int buf) {
        const uint32_t bbase = 1024u + (uint32_t)buf * 65536u;
        const int kb = ch * 64;
        #pragma unroll
        for (int it = 0; it < 4; it++) {
            int row = lrow0 + it * 32;
            uint32_t sw = SMEM_SWIZZLE_128B((uint32_t)(row * 128 + lc16 * 16));
            const __nv_bfloat16* gA = g_xhi + (size_t)(m0 + row) * INP + kb + lc16 * 8;
            const __nv_bfloat16* gAl= g_xlo + (size_t)(m0 + row) * INP + kb + lc16 * 8;
            const __nv_bfloat16* gB = g_whi + (size_t)(n0 + row) * INP + kb + lc16 * 8;
            const __nv_bfloat16* gBl= g_wlo + (size_t)(n0 + row) * INP + kb + lc16 * 8;
            cp_async16(sb + bbase +         sw, gA);
            cp_async16(sb + bbase + 16384 + sw, gAl);
            cp_async16(sb + bbase + 32768 + sw, gB);
            cp_async16(sb + bbase + 49152 + sw, gBl);
        }
        cp_async_commit();
    };

    issue_chunk(0, 0);

    for (int ch = 0; ch < 8; ch++) {
        const int buf = ch & 1;
        if (ch < 7) issue_chunk(ch + 1, buf ^ 1);
        if (ch < 7) cp_async_wait<1>(); else cp_async_wait<0>();
        __syncthreads();

        const uint32_t bbase = sb + 1024u + (uint32_t)buf * 65536u;
        #pragma unroll
        for (int ks = 0; ks < 4; ks++) {
            uint32_t ahi[4][4], alo[4][4], bhi[4][4], blo[4][4];
            #pragma unroll
            for (int im = 0; im < 4; im++) {
                uint32_t sw = SMEM_SWIZZLE_128B(aOff[im] + ks * 32);
                ldmatrix_x4(ahi[im], bbase + sw);
                ldmatrix_x4(alo[im], bbase + 16384 + sw);
            }
            #pragma unroll
            for (int ib = 0; ib < 2; ib++) {
                uint32_t sw = SMEM_SWIZZLE_128B(bOff[ib] + ks * 32);
                ldmatrix_x4(bhi[ib], bbase + 32768 + sw);
                ldmatrix_x4(blo[ib], bbase + 49152 + sw);
            }
            #pragma unroll
            for (int im = 0; im < 4; im++) {
                #pragma unroll
                for (int jn = 0; jn < 4; jn++) {
                    uint32_t* bh = &bhi[jn >> 1][(jn & 1) * 2];
                    uint32_t* bl = &blo[jn >> 1][(jn & 1) * 2];
                    mma_bf16(c[im][jn], ahi[im], bh);
                    mma_bf16(c[im][jn], ahi[im], bl);
                    mma_bf16(c[im][jn], alo[im], bh);
                }
            }
        }
        __syncthreads();
    }

    float* cs = (float*)(smem + 1024);   // [128][129]
    const int crow = lane >> 2;
    const int ccol = (lane & 3) * 2;
    #pragma unroll
    for (int im = 0; im < 4; im++) {
        #pragma unroll
        for (int jn = 0; jn < 4; jn++) {
            int r0 = wm + 16 * im + crow;
            int cc = wn + 8 * jn + ccol;
            cs[r0 * 129 + cc]           = c[im][jn][0];
            cs[r0 * 129 + cc + 1]       = c[im][jn][1];
            cs[(r0 + 8) * 129 + cc]     = c[im][jn][2];
            cs[(r0 + 8) * 129 + cc + 1] = c[im][jn][3];
        }
    }
    __syncthreads();

    const int t0 = blockIdx.y * 4;
    for (int i = 0; i < 64; i++) {
        int ro = wid * 64 + i;
        int tl = ro >> 7, n = ro & 127;
        float v = cs[(tl * 32 + lane) * 129 + n] + bias_sm[n];
        g_xw[((size_t)(t0 + tl) * G4 + n0 + n) * BATCH + lane] = v;
    }
}

// ---------------- phase 2: tensor-core persistent recurrence v2 ----------------
// 128 CTAs x 256 threads (8 warps). CTA owns 4 hidden units -> 16 gate cols
// (gate-major: local n = g*4+u -> global gcol = u0+u+512g).
// Warp w owns K-chunk w (64 k): issues AND consumes its own cp.asyncs.
// Warps 4-7 additionally prefetch xw(t+1) into a double-buffered slot.
// smem bytes:
//   [0      .. 32768)  h hi, 8 chunks of [32 b][64 k] bf16 (4KB, swizzled)
//   [32768  .. 65536)  h lo
//   [65536  .. 81920)  U hi, 8 chunks of [16 n][64 k] bf16 (2KB, swizzled)
//   [81920  .. 98304)  U lo
//   [98304  ..102400)  xw double buffer, 2 x [16 n][32 b] fp32
//   [102400 ..120832)  partials [8 w][32 m][18 pad] fp32
#define R_HHI 0
#define R_HLO 32768
#define R_UHI 65536
#define R_ULO 81920
#define R_XW  98304
#define R_P   102400
#define REC2_SMEM_BYTES 120832
#define NCTA  128

__global__ __launch_bounds__(256, 1) void lstm_rec_tc_kernel(
    const float* __restrict__ U, float* __restrict__ out, int write_tail)
{
    extern __shared__ char smem[];
    const uint32_t sb = smem_to_u32(smem);
    const int tid  = threadIdx.x;
    const int wid  = tid >> 5;
    const int lane = tid & 31;
    const int u0   = blockIdx.x * 4;

    // ---- load U slice -> smem bf16 hi/lo, chunked+swizzled ----
    for (int i = tid; i < 16 * HID; i += 256) {
        int k = i >> 4, n = i & 15;
        int gcol = u0 + (n & 3) + 512 * (n >> 2);
        float v = U[(size_t)k * G4 + gcol];
        __nv_bfloat16 hi = __float2bfloat16(v);
        __nv_bfloat16 lo = __float2bfloat16(v - __bfloat162float(hi));
        int c = k >> 6, ko = k & 63;
        uint32_t sw = SMEM_SWIZZLE_128B((uint32_t)(n * 128 + ko * 2));
        *(__nv_bfloat16*)(smem + R_UHI + c * 2048 + sw) = hi;
        *(__nv_bfloat16*)(smem + R_ULO + c * 2048 + sw) = lo;
    }

    // ldmatrix lane address parts
    const uint32_t aRow = (uint32_t)(lane & 15);
    const uint32_t aCol = (uint32_t)(((lane >> 4) & 1) * 16);
    const uint32_t bRow = (uint32_t)(((lane >> 4) & 1) * 8 + (lane & 7));
    const uint32_t bCol = (uint32_t)(((lane >> 3) & 1) * 16);
    uint32_t aBase[2];
    #pragma unroll
    for (int mt = 0; mt < 2; mt++) aBase[mt] = (uint32_t)(mt * 16 + aRow) * 128 + aCol;
    const uint32_t bBase = bRow * 128 + bCol;   // 16 U rows per chunk

    // reduce mapping: thread (tid<128) owns (b = tid>>2, u = tid&3)
    const int rb = tid >> 2;
    const int ua = tid & 3;
    float c_state = 0.f;

    float* p_sm = (float*)(smem + R_P);

    // xw prefetch: warps 4-7 (threads 128..255), 1 cp.async16 each, slot = t&1
    auto issue_xw = [&](int t) {
        if (tid >= 128) {
            int idx = tid - 128;
            int n = idx >> 3, seg = idx & 7;
            int gcol = u0 + (n & 3) + 512 * (n >> 2);
            cp_async16(sb + R_XW + (uint32_t)((t & 1) * 2048 + n * 128 + seg * 16),
                       g_xw + ((size_t)t * G4 + gcol) * BATCH + seg * 4);
            cp_async_commit();
        }
    };
    // h chunk load: warp w loads chunk w (its own cp.asyncs)
    auto issue_h_chunk = [&](int R, int cc) {
        const __nv_bfloat16* hhi = g_hb[R][0];
        const __nv_bfloat16* hlo = g_hb[R][1];
        #pragma unroll
        for (int j = 0; j < 8; j++) {
            int idx = lane + 32 * j;
            int b = idx >> 3, seg = idx & 7;
            uint32_t sw = SMEM_SWIZZLE_128B((uint32_t)(b * 128 + seg * 16));
            cp_async16(sb + R_HHI + cc * 4096 + sw, hhi + b * 512 + cc * 64 + seg * 8);
            cp_async16(sb + R_HLO + cc * 4096 + sw, hlo + b * 512 + cc * 64 + seg * 8);
        }
        cp_async_commit();
    };

    __syncthreads();            // U slice ready
    issue_xw(0);

    for (int t = 0; t < T_STEPS; t++) {
        const int R = t & 1;

        // warp w loads chunk w
        issue_h_chunk(R, wid);

        float cfr[2][2][4];
        #pragma unroll
        for (int mt = 0; mt < 2; mt++)
            #pragma unroll
            for (int jn = 0; jn < 2; jn++)
                #pragma unroll
                for (int q = 0; q < 4; q++) cfr[mt][jn][q] = 0.f;

        // drain own groups (warps 4-7 also drain the old xw prefetch,
        // issued a full step earlier -- long since complete)
        cp_async_wait<0>();

        const uint32_t hbse = sb + R_HHI + wid * 4096;
        const uint32_t ubse = sb + R_UHI + wid * 2048;
        #pragma unroll
        for (int kt = 0; kt < 4; kt++) {
            uint32_t ahi[2][4], alo[2][4], bhi[4], blo[4];
            #pragma unroll
            for (int mt = 0; mt < 2; mt++) {
                uint32_t sw = SMEM_SWIZZLE_128B(aBase[mt] + kt * 32);
                ldmatrix_x4(ahi[mt], hbse + sw);
                ldmatrix_x4(alo[mt], hbse + 32768 + sw);
            }
            {
                uint32_t sw = SMEM_SWIZZLE_128B(bBase + kt * 32);
                ldmatrix_x4(bhi, ubse + sw);
                ldmatrix_x4(blo, ubse + 16384 + sw);
            }
            #pragma unroll
            for (int mt = 0; mt < 2; mt++) {
                #pragma unroll
                for (int jn = 0; jn < 2; jn++) {
                    uint32_t* bh = &bhi[jn * 2];
                    uint32_t* bl = &blo[jn * 2];
                    mma_bf16(cfr[mt][jn], ahi[mt], bh);
                    mma_bf16(cfr[mt][jn], ahi[mt], bl);
                    mma_bf16(cfr[mt][jn], alo[mt], bh);
                }
            }
        }

        // write K-partials to smem [w][m][18]
        {
            const int m  = lane >> 2;
            const int nn = 2 * (lane & 3);
            #pragma unroll
            for (int mt = 0; mt < 2; mt++) {
                #pragma unroll
                for (int jn = 0; jn < 2; jn++) {
                    int row = wid * 32 + mt * 16 + m;
                    int col = jn * 8 + nn;
                    *(float2*)&p_sm[row * 18 + col] =
                        make_float2(cfr[mt][jn][0], cfr[mt][jn][1]);
                    *(float2*)&p_sm[(row + 8) * 18 + col] =
                        make_float2(cfr[mt][jn][2], cfr[mt][jn][3]);
                }
            }
        }
        __syncthreads();   // partials + xw(t) visible to all threads

        // prefetch xw for next step (different slot than the one being read)
        if (t + 1 < T_STEPS) issue_xw(t + 1);

        // reduce + activations (tid < 128): thread owns (rb, ua)
        if (tid < 128) {
            const float* xw_sm = (const float*)(smem + R_XW + (t & 1) * 2048);
            float s[4];
            #pragma unroll
            for (int g = 0; g < 4; g++) {
                int n = g * 4 + ua;
                float v = xw_sm[n * 32 + rb];
                #pragma unroll
                for (int w = 0; w < 8; w++)
                    v += p_sm[(w * 32 + rb) * 18 + n];
                s[g] = v;
            }
            float ig = sigmoidf_(s[0]);
            float fg = sigmoidf_(s[1]);
            float gg = tanhf(s[2]);
            float og = sigmoidf_(s[3]);
            float cnew = fg * c_state + ig * gg;
            float hnew = og * tanhf(cnew);
            c_state = cnew;

            out[((size_t)t * BATCH + rb) * HID + u0 + ua] = hnew;
            __nv_bfloat16 hh = __float2bfloat16(hnew);
            __nv_bfloat16 hl = __float2bfloat16(hnew - __bfloat162float(hh));
            g_hb[R ^ 1][0][rb * 512 + u0 + ua] = hh;
            g_hb[R ^ 1][1][rb * 512 + u0 + ua] = hl;
            if (write_tail && t == T_STEPS - 1) {
                out[(size_t)T_STEPS * BATCH * HID + (size_t)rb * HID + u0 + ua] = hnew;
                out[(size_t)T_STEPS * BATCH * HID + BATCH * HID
                    + (size_t)rb * HID + u0 + ua] = cnew;
            }
        }
        __syncthreads();   // h stores done before the release below

        // grid barrier
        if (t + 1 < T_STEPS) {
            if (tid == 0) {
                unsigned int target = (unsigned int)NCTA * (unsigned int)(t + 1);
                asm volatile("red.release.gpu.add.u32 [%0], %1;"
                             :: "l"(&g_bar), "r"(1u) : "memory");
                unsigned int v;
                do {
                    asm volatile("ld.acquire.gpu.u32 %0, [%1];"
                                 : "=r"(v) : "l"(&g_bar) : "memory");
                } while (v < target);
            }
            __syncthreads();
        }
    }
}

// ---------------- launch ----------------
extern "C" void kernel_launch(void* const* d_in, const int* in_sizes, int n_in,
                              void* d_out, int out_size)
{
    const float* x    = (const float*)d_in[0]; // (T,B,I)
    const float* W    = (const float*)d_in[1]; // (I,4H)
    const float* U    = (const float*)d_in[2]; // (H,4H)
    const float* bias = (const float*)d_in[3]; // (4H,)
    float* out = (float*)d_out;

    const long long need_tail = (long long)T_STEPS * BATCH * HID + 2LL * BATCH * HID;
    int write_tail = ((long long)out_size >= need_tail) ? 1 : 0;

    static int configured = 0;
    if (!configured) {
        cudaFuncSetAttribute(xw_tc_kernel,
                             cudaFuncAttributeMaxDynamicSharedMemorySize,
                             GEMM_SMEM_BYTES);
        cudaFuncSetAttribute(lstm_rec_tc_kernel,
                             cudaFuncAttributeMaxDynamicSharedMemorySize,
                             REC2_SMEM_BYTES);
        configured = 1;
    }

    lstm_init_kernel<<<64, 256>>>();
    xcvt_kernel<<<(MTOT * INP) / 4 / 256, 256>>>(x);
    wcvt_kernel<<<dim3(G4 / 32, INP / 32), 256>>>(W);
    xw_tc_kernel<<<dim3(16, 256), 256, GEMM_SMEM_BYTES>>>(bias);
    lstm_rec_tc_kernel<<<NCTA, 256, REC2_SMEM_BYTES>>>(U, out, write_tail);
}